// round 10
// baseline (speedup 1.0000x reference)
#include <cuda_runtime.h>
#include <math.h>

#define N_IMG 32
#define ROWS_PER_IMG 262144              // 128*128*64 / 4 float4-rows per image
#define K1_CTAS_PER_IMG 64
#define K1_THREADS 256
#define ROWS_PER_CTA (ROWS_PER_IMG / K1_CTAS_PER_IMG)   // 4096
#define ROWS_PER_THREAD (ROWS_PER_CTA / K1_THREADS)     // 16

// Deterministic scratch (no device allocation allowed).
__device__ float g_part[N_IMG][K1_CTAS_PER_IMG][14];
__device__ float g_coef[N_IMG][8];   // w0..w3, b, pad

// 256-bit read-only load with L2 evict_last retention. On sm_103a the
// evict_last modifier is only legal at 256-bit width (.v8.b32), which is why
// the scalar-float4 version failed ptxas. The 128 MiB input nearly fits the
// 126 MB L2 and is re-read every replay (K1 + K3, and L2 persists across
// launches/replays), so high retention priority converts the read streams
// into L2 hits in steady state.
__device__ __forceinline__ void ldg_el8(const float4* p, float4& a, float4& b) {
    unsigned r0, r1, r2, r3, r4, r5, r6, r7;
    asm("ld.global.nc.L2::evict_last.v8.b32 {%0,%1,%2,%3,%4,%5,%6,%7}, [%8];"
        : "=r"(r0), "=r"(r1), "=r"(r2), "=r"(r3),
          "=r"(r4), "=r"(r5), "=r"(r6), "=r"(r7)
        : "l"(p));
    a.x = __uint_as_float(r0); a.y = __uint_as_float(r1);
    a.z = __uint_as_float(r2); a.w = __uint_as_float(r3);
    b.x = __uint_as_float(r4); b.y = __uint_as_float(r5);
    b.z = __uint_as_float(r6); b.w = __uint_as_float(r7);
}

// ---------------------------------------------------------------------------
// K1: per-image raw moments. Every float4 of the image is one patches row.
// Thread t owns row pair (t*2, t*2+1) advancing by 512 rows per step:
// each LDG.256 is 32B-aligned and warp-coalesced. 4 loads batched (MLP=4
// at 32B each = 128B/thread in flight).
// ---------------------------------------------------------------------------
__global__ void __launch_bounds__(K1_THREADS) k1_reduce(const float4* __restrict__ in) {
    const int img = blockIdx.x >> 6;
    const int cta = blockIdx.x & 63;
    const float4* p = in + (size_t)img * ROWS_PER_IMG + cta * ROWS_PER_CTA
                        + threadIdx.x * 2;

    float s0 = 0.f, s1 = 0.f, s2 = 0.f, s3 = 0.f;
    float q00 = 0.f, q01 = 0.f, q02 = 0.f, q03 = 0.f;
    float q11 = 0.f, q12 = 0.f, q13 = 0.f;
    float q22 = 0.f, q23 = 0.f, q33 = 0.f;

#pragma unroll
    for (int g = 0; g < 2; g++) {
        float4 buf[8];
#pragma unroll
        for (int j = 0; j < 4; j++)
            ldg_el8(p + (g * 4 + j) * (K1_THREADS * 2), buf[j * 2], buf[j * 2 + 1]);
#pragma unroll
        for (int j = 0; j < 8; j++) {
            float4 v = buf[j];
            s0 += v.x; s1 += v.y; s2 += v.z; s3 += v.w;
            q00 = fmaf(v.x, v.x, q00); q01 = fmaf(v.x, v.y, q01);
            q02 = fmaf(v.x, v.z, q02); q03 = fmaf(v.x, v.w, q03);
            q11 = fmaf(v.y, v.y, q11); q12 = fmaf(v.y, v.z, q12);
            q13 = fmaf(v.y, v.w, q13);
            q22 = fmaf(v.z, v.z, q22); q23 = fmaf(v.z, v.w, q23);
            q33 = fmaf(v.w, v.w, q33);
        }
    }

    float vals[14] = {s0, s1, s2, s3, q00, q01, q02, q03, q11, q12, q13, q22, q23, q33};

    __shared__ float sm[8][14];
    const int lane = threadIdx.x & 31;
    const int warp = threadIdx.x >> 5;

#pragma unroll
    for (int i = 0; i < 14; i++) {
        float v = vals[i];
#pragma unroll
        for (int off = 16; off; off >>= 1)
            v += __shfl_down_sync(0xffffffffu, v, off);
        if (lane == 0) sm[warp][i] = v;
    }
    __syncthreads();
    if (warp == 0 && lane < 14) {
        float v = 0.f;
#pragma unroll
        for (int w = 0; w < 8; w++) v += sm[w][lane];
        g_part[img][cta][lane] = v;
    }
}

// ---------------------------------------------------------------------------
// K2: per-image final reduction (fp64, non-iterative), stats, then SHIFTED
// gram E = Gram - N*I in fp64 (cancellation-safe) and Jacobi in fp32 on E
// with a real convergence break. (Unchanged.)
// ---------------------------------------------------------------------------
__global__ void k2_solve() {
    const int img = blockIdx.x;
    const int t = threadIdx.x;
    __shared__ double red[14];

    if (t < 14) {
        double acc = 0.0;
#pragma unroll 4
        for (int c = 0; c < K1_CTAS_PER_IMG; c++)
            acc += (double)g_part[img][c][t];
        red[t] = acc;
    }
    __syncthreads();

    if (t == 0) {
        const double N = (double)ROWS_PER_IMG;
        double S[4] = {red[0], red[1], red[2], red[3]};
        double Q[4][4];
        Q[0][0] = red[4];  Q[0][1] = red[5];  Q[0][2] = red[6];  Q[0][3] = red[7];
        Q[1][1] = red[8];  Q[1][2] = red[9];  Q[1][3] = red[10];
        Q[2][2] = red[11]; Q[2][3] = red[12]; Q[3][3] = red[13];
        Q[1][0] = Q[0][1]; Q[2][0] = Q[0][2]; Q[3][0] = Q[0][3];
        Q[2][1] = Q[1][2]; Q[3][1] = Q[1][3]; Q[3][2] = Q[2][3];

        double mu[4], inv[4];
        bool zerov[4];
#pragma unroll
        for (int i = 0; i < 4; i++) {
            mu[i] = S[i] / N;
            double var = Q[i][i] / N - mu[i] * mu[i];
            if (var < 0.0) var = 0.0;
            double sd = sqrt(var);
            zerov[i] = (sd == 0.0);
            inv[i] = zerov[i] ? 0.0 : 1.0 / sd;
        }

        float A[4][4];
        for (int i = 0; i < 4; i++)
            for (int j = 0; j < 4; j++) {
                double g = (Q[i][j] - N * mu[i] * mu[j]) * inv[i] * inv[j];
                if (i == j) g = zerov[i] ? -N : 0.0;
                A[i][j] = (float)g;
            }

        float V[4][4] = {{1,0,0,0},{0,1,0,0},{0,0,1,0},{0,0,0,1}};
        for (int sweep = 0; sweep < 8; sweep++) {
            float off = fabsf(A[0][1]) + fabsf(A[0][2]) + fabsf(A[0][3])
                      + fabsf(A[1][2]) + fabsf(A[1][3]) + fabsf(A[2][3]);
            if (off < 1e-3f) break;   // entries O(500); fp32 noise floor
            for (int p = 0; p < 3; p++) {
                for (int q = p + 1; q < 4; q++) {
                    float apq = A[p][q];
                    if (fabsf(apq) == 0.0f) continue;
                    float theta = (A[q][q] - A[p][p]) / (2.0f * apq);
                    float tt = ((theta >= 0.0f) ? 1.0f : -1.0f)
                             / (fabsf(theta) + sqrtf(theta * theta + 1.0f));
                    float c = rsqrtf(tt * tt + 1.0f);
                    float s = tt * c;
                    for (int k = 0; k < 4; k++) {
                        float akp = A[k][p], akq = A[k][q];
                        A[k][p] = c * akp - s * akq;
                        A[k][q] = s * akp + c * akq;
                    }
                    for (int k = 0; k < 4; k++) {
                        float apk = A[p][k], aqk = A[q][k];
                        A[p][k] = c * apk - s * aqk;
                        A[q][k] = s * apk + c * aqk;
                    }
                    for (int k = 0; k < 4; k++) {
                        float vkp = V[k][p], vkq = V[k][q];
                        V[k][p] = c * vkp - s * vkq;
                        V[k][q] = s * vkp + c * vkq;
                    }
                }
            }
        }

        int best = 0;
        for (int i = 1; i < 4; i++)
            if (A[i][i] > A[best][best]) best = i;

        float v[4]; float sum = 0.0f;
#pragma unroll
        for (int i = 0; i < 4; i++) { v[i] = V[i][best]; sum += v[i]; }
        double sgn = (sum < 0.0f) ? -1.0 : 1.0;

        double b = 0.0;
#pragma unroll
        for (int i = 0; i < 4; i++) {
            double wi = sgn * (double)v[i] * inv[i];
            g_coef[img][i] = (float)wi;
            b -= wi * mu[i];
        }
        g_coef[img][4] = (float)b;
    }
}

// ---------------------------------------------------------------------------
// K3: projection, 4 outputs/thread via 2x LDG.256 evict_last (input base is
// 64B-aligned: offset = 16B*(16*row + cgb), cgb in {0,4,8,12}) + 1x STG.128
// streaming (evict_first) so the write stream can't displace pinned input.
// Reverse block order kept (MRU-first on the first replay).
// ---------------------------------------------------------------------------
__global__ void __launch_bounds__(256) k3_project(const float4* __restrict__ in,
                                                  float4* __restrict__ out) {
    const int blk = gridDim.x - 1 - blockIdx.x;          // reverse traversal
    const int o4 = blk * 256 + threadIdx.x;              // float4 output index
    const int img = o4 >> 16;          // 65536 float4-outputs per image
    const int lo4 = o4 & 65535;
    const int S  = lo4 >> 4;           // 16 float4 per (h2,w2) block
    const int c4 = lo4 & 15;           // which float4 within the 64 channels
    const int h2 = S >> 6, w2i = S & 63;
    const int pp = c4 >> 2;            // ph*2 + pw (4 c_out share one patch pos)
    const int cgb = (c4 & 3) << 2;     // base channel-group 0,4,8,12
    const int ph = pp >> 1, pw = pp & 1;
    const int m = (((h2 << 1) + ph) * 128 + ((w2i << 1) + pw)) * 16 + cgb;

    const float4* src = in + (size_t)img * ROWS_PER_IMG + m;
    float4 x0, x1, x2, x3;
    ldg_el8(src + 0, x0, x1);
    ldg_el8(src + 2, x2, x3);

    const float* cf = g_coef[img];
    const float w0 = cf[0], w1 = cf[1], w2c = cf[2], w3 = cf[3], b = cf[4];

    float4 r;
    r.x = fmaf(w0, x0.x, fmaf(w1, x0.y, fmaf(w2c, x0.z, fmaf(w3, x0.w, b))));
    r.y = fmaf(w0, x1.x, fmaf(w1, x1.y, fmaf(w2c, x1.z, fmaf(w3, x1.w, b))));
    r.z = fmaf(w0, x2.x, fmaf(w1, x2.y, fmaf(w2c, x2.z, fmaf(w3, x2.w, b))));
    r.w = fmaf(w0, x3.x, fmaf(w1, x3.y, fmaf(w2c, x3.z, fmaf(w3, x3.w, b))));
    __stcs(out + o4, r);
}

extern "C" void kernel_launch(void* const* d_in, const int* in_sizes, int n_in,
                              void* d_out, int out_size) {
    const float4* in = (const float4*)d_in[0];
    float4* out = (float4*)d_out;
    k1_reduce<<<N_IMG * K1_CTAS_PER_IMG, K1_THREADS>>>(in);
    k2_solve<<<N_IMG, 64>>>();
    // 32*262144 float outputs / 4 per thread / 256 per block = 8192 blocks
    k3_project<<<(N_IMG * ROWS_PER_IMG) / 4 / 256, 256>>>(in, out);
}